// round 1
// baseline (speedup 1.0000x reference)
#include <cuda_runtime.h>
#include <math.h>

#define NN 50000
#define EE 800000
#define BB 64
#define DD 64
#define HHD 2          // heads
#define GG 50
#define HIDN 128
#define HD 128         // H*D
#define LLAYERS 3

// ---- scratch (static device arrays; no allocation allowed) ----
__device__ float g_r[EE];
__device__ float g_C[EE];
__device__ float g_x[NN * DD];
__device__ float g_h[NN * HD];
__device__ float g_el[NN * HHD];
__device__ float g_er[NN * HHD];
__device__ float g_agg[NN * HD];
__device__ float g_den[NN * HHD];

__device__ __forceinline__ float ssp(float x) {
    // softplus(x) - log(2), numerically stable
    return fmaxf(x, 0.f) + log1pf(expf(-fabsf(x))) - 0.69314718055994531f;
}

// ---------------- edge geometry: r and cosine cutoff ----------------
__global__ void edge_geom(const float* __restrict__ R,
                          const int* __restrict__ src,
                          const int* __restrict__ dst) {
    int e = blockIdx.x * blockDim.x + threadIdx.x;
    if (e >= EE) return;
    int s = src[e], d = dst[e];
    float dx = R[s * 3 + 0] - R[d * 3 + 0];
    float dy = R[s * 3 + 1] - R[d * 3 + 1];
    float dz = R[s * 3 + 2] - R[d * 3 + 2];
    float r = sqrtf(dx * dx + dy * dy + dz * dz);
    g_r[e] = r;
    float c = 0.5f * (cosf(r * 0.39269908169872414f) + 1.0f);  // pi/8
    g_C[e] = (r < 8.0f) ? c : 0.0f;
}

// ---------------- embedding gather ----------------
__global__ void embed_kernel(const int* __restrict__ Z,
                             const float* __restrict__ emb) {
    int i = blockIdx.x * blockDim.x + threadIdx.x;
    if (i >= NN * DD) return;
    int n = i >> 6, d = i & 63;
    g_x[i] = emb[Z[n] * DD + d];
}

// ---------------- per-node: h = x @ fc_w, el/er attention logits ----------------
__global__ void node_pre(const float* __restrict__ fcw,
                         const float* __restrict__ al,
                         const float* __restrict__ ar) {
    int n = blockIdx.x;
    int t = threadIdx.x;  // 128 threads
    __shared__ float xs[DD];
    __shared__ float red_l[HHD];
    __shared__ float red_r[HHD];
    if (t < DD) xs[t] = g_x[n * DD + t];
    if (t < HHD) { red_l[t] = 0.f; red_r[t] = 0.f; }
    __syncthreads();
    float acc = 0.f;
#pragma unroll
    for (int k = 0; k < DD; k++) acc = fmaf(xs[k], fcw[k * HD + t], acc);
    g_h[n * HD + t] = acc;
    int head = t >> 6, d = t & 63;
    float pl = acc * al[head * DD + d];
    float pr = acc * ar[head * DD + d];
#pragma unroll
    for (int o = 16; o > 0; o >>= 1) {
        pl += __shfl_down_sync(0xffffffffu, pl, o);
        pr += __shfl_down_sync(0xffffffffu, pr, o);
    }
    if ((t & 31) == 0) { atomicAdd(&red_l[head], pl); atomicAdd(&red_r[head], pr); }
    __syncthreads();
    if (t < HHD) { g_el[n * HHD + t] = red_l[t]; g_er[n * HHD + t] = red_r[t]; }
}

// ---------------- zero aggregation scratch ----------------
__global__ void zero_agg() {
    int i = blockIdx.x * blockDim.x + threadIdx.x;
    if (i < NN * HD) g_agg[i] = 0.f;
    if (i < NN * HHD) g_den[i] = 0.f;
}

// ---------------- fused edge pass: filter MLP + message + attention + aggregate ----------------
__global__ void edge_pass(const int* __restrict__ src,
                          const int* __restrict__ dst,
                          const float* __restrict__ off,
                          const float* __restrict__ wid,
                          const float* __restrict__ w1,
                          const float* __restrict__ b1,
                          const float* __restrict__ w2,
                          const float* __restrict__ b2) {
    int e = blockIdx.x;
    int t = threadIdx.x;  // 128 threads
    __shared__ float gs[GG];
    __shared__ float hid[HIDN];
    __shared__ float exs[HHD];

    float r = g_r[e];
    int s = src[e], d = dst[e];

    if (t < GG) {
        float w = wid[t];
        float coef = -0.5f / (w * w);
        float dr = r - off[t];
        gs[t] = expf(coef * dr * dr);
    }
    if (t < HHD) {
        float ev = g_el[s * HHD + t] + g_er[d * HHD + t];
        ev = ev > 0.f ? ev : 0.2f * ev;  // leaky_relu
        float ex = expf(ev);             // softmax without max-shift (shift-invariant)
        exs[t] = ex;
        atomicAdd(&g_den[d * HHD + t], ex);
    }
    __syncthreads();

    // hid = ssp(gs @ W1 + b1)
    float acc = b1[t];
#pragma unroll
    for (int g = 0; g < GG; g++) acc = fmaf(gs[g], w1[g * HD + t], acc);
    hid[t] = ssp(acc);
    __syncthreads();

    // w = hid @ W2 + b2
    float acc2 = b2[t];
#pragma unroll 8
    for (int k = 0; k < HIDN; k++) acc2 = fmaf(hid[k], w2[k * HD + t], acc2);

    float C = g_C[e];
    int head = t >> 6;
    float msg = g_h[s * HD + t] * acc2 * C * exs[head];
    atomicAdd(&g_agg[d * HD + t], msg);
}

// ---------------- per-node update: normalize, ssp, 2-layer MLP, residual ----------------
__global__ void node_update(const float* __restrict__ m1,
                            const float* __restrict__ mb1,
                            const float* __restrict__ m2,
                            const float* __restrict__ mb2) {
    int n = blockIdx.x;
    int t = threadIdx.x;  // 64 threads
    __shared__ float v[HD];
    __shared__ float t1[DD];
#pragma unroll
    for (int j = t; j < HD; j += DD) {
        int head = j >> 6;
        float den = g_den[n * HHD + head];
        float a = g_agg[n * HD + j];
        a = (den > 0.f) ? a / den : 0.f;
        v[j] = ssp(a);
    }
    __syncthreads();
    float acc = mb1[t];
#pragma unroll 8
    for (int k = 0; k < HD; k++) acc = fmaf(v[k], m1[k * DD + t], acc);
    t1[t] = ssp(acc);
    __syncthreads();
    float acc2 = mb2[t];
#pragma unroll
    for (int k = 0; k < DD; k++) acc2 = fmaf(t1[k], m2[k * DD + t], acc2);
    g_x[n * DD + t] += acc2;
}

// ---------------- output head ----------------
__global__ void zero_out(float* out) {
    if (threadIdx.x < BB) out[threadIdx.x] = 0.f;
}

__global__ void out_kernel(const float* __restrict__ w1,
                           const float* __restrict__ b1,
                           const float* __restrict__ w2,
                           const float* __restrict__ b2,
                           const int* __restrict__ gid,
                           float* __restrict__ out) {
    int n = blockIdx.x;
    int t = threadIdx.x;  // 128 threads
    __shared__ float xs[DD];
    __shared__ float red[4];
    if (t < DD) xs[t] = g_x[n * DD + t];
    __syncthreads();
    float acc = b1[t];
#pragma unroll
    for (int k = 0; k < DD; k++) acc = fmaf(xs[k], w1[k * 128 + t], acc);
    float p = ssp(acc) * w2[t];
#pragma unroll
    for (int o = 16; o > 0; o >>= 1) p += __shfl_down_sync(0xffffffffu, p, o);
    if ((t & 31) == 0) red[t >> 5] = p;
    __syncthreads();
    if (t == 0) {
        float hh = red[0] + red[1] + red[2] + red[3] + b2[0];
        // * STD + MEAN with STD=1, MEAN=0 -> identity
        atomicAdd(&out[gid[n]], hh);
    }
}

extern "C" void kernel_launch(void* const* d_in, const int* in_sizes, int n_in,
                              void* d_out, int out_size) {
    const float* R    = (const float*)d_in[0];
    const int*   Z    = (const int*)d_in[1];
    const int*   src  = (const int*)d_in[2];
    const int*   dst  = (const int*)d_in[3];
    const int*   gid  = (const int*)d_in[4];
    const float* emb  = (const float*)d_in[5];
    const float* off  = (const float*)d_in[6];
    const float* wid  = (const float*)d_in[7];
    const float* fcw  = (const float*)d_in[8];
    const float* al   = (const float*)d_in[9];
    const float* ar   = (const float*)d_in[10];
    const float* fw1  = (const float*)d_in[11];
    const float* fb1  = (const float*)d_in[12];
    const float* fw2  = (const float*)d_in[13];
    const float* fb2  = (const float*)d_in[14];
    const float* m1   = (const float*)d_in[15];
    const float* mb1  = (const float*)d_in[16];
    const float* m2   = (const float*)d_in[17];
    const float* mb2  = (const float*)d_in[18];
    const float* ow1  = (const float*)d_in[19];
    const float* ob1  = (const float*)d_in[20];
    const float* ow2  = (const float*)d_in[21];
    const float* ob2  = (const float*)d_in[22];
    float* out = (float*)d_out;

    edge_geom<<<(EE + 255) / 256, 256>>>(R, src, dst);
    embed_kernel<<<(NN * DD + 255) / 256, 256>>>(Z, emb);

    for (int l = 0; l < LLAYERS; l++) {
        node_pre<<<NN, 128>>>(fcw + l * DD * HD, al + l * HHD * DD, ar + l * HHD * DD);
        zero_agg<<<(NN * HD + 255) / 256, 256>>>();
        edge_pass<<<EE, 128>>>(src, dst, off, wid,
                               fw1 + l * GG * HD, fb1 + l * HD,
                               fw2 + l * HIDN * HD, fb2 + l * HD);
        node_update<<<NN, 64>>>(m1 + l * HD * DD, mb1 + l * DD,
                                m2 + l * DD * DD, mb2 + l * DD);
    }

    zero_out<<<1, 64>>>(out);
    out_kernel<<<NN, 128>>>(ow1, ob1, ow2, ob2, gid, out);
}

// round 2
// speedup vs baseline: 8.5496x; 8.5496x over previous
#include <cuda_runtime.h>
#include <math.h>

#define NN 50000
#define EE 800000
#define BB 64
#define DD 64
#define HHD 2          // heads
#define GG 50
#define HIDN 128
#define HD 128         // H*D
#define LLAYERS 3
#define TBL 8192       // table resolution over [0, 8)
#define TBL_SCALE 1024.0f   // TBL / 8.0

// ---- scratch (static device arrays; no allocation allowed) ----
__device__ float g_r[EE];
__device__ float g_x[NN * DD];
__device__ float g_h[NN * HD];
__device__ float g_el[NN * HHD];
__device__ float g_er[NN * HHD];
__device__ float g_agg[NN * HD];
__device__ float g_den[NN * HHD];
__device__ float g_T[(TBL + 1) * HD];   // w(r)*C(r) lookup, 4.2 MB

__device__ __forceinline__ float ssp(float x) {
    // softplus(x) - log(2), numerically stable
    return fmaxf(x, 0.f) + log1pf(expf(-fabsf(x))) - 0.69314718055994531f;
}

// ---------------- edge geometry: r ----------------
__global__ void edge_geom(const float* __restrict__ R,
                          const int* __restrict__ src,
                          const int* __restrict__ dst) {
    int e = blockIdx.x * blockDim.x + threadIdx.x;
    if (e >= EE) return;
    int s = src[e], d = dst[e];
    float dx = R[s * 3 + 0] - R[d * 3 + 0];
    float dy = R[s * 3 + 1] - R[d * 3 + 1];
    float dz = R[s * 3 + 2] - R[d * 3 + 2];
    g_r[e] = sqrtf(dx * dx + dy * dy + dz * dz);
}

// ---------------- embedding gather ----------------
__global__ void embed_kernel(const int* __restrict__ Z,
                             const float* __restrict__ emb) {
    int i = blockIdx.x * blockDim.x + threadIdx.x;
    if (i >= NN * DD) return;
    int n = i >> 6, d = i & 63;
    g_x[i] = emb[Z[n] * DD + d];
}

// ---------------- per-node: h = x @ fc_w, el/er attention logits ----------------
__global__ void node_pre(const float* __restrict__ fcw,
                         const float* __restrict__ al,
                         const float* __restrict__ ar) {
    int n = blockIdx.x;
    int t = threadIdx.x;  // 128 threads
    __shared__ float xs[DD];
    __shared__ float red_l[HHD];
    __shared__ float red_r[HHD];
    if (t < DD) xs[t] = g_x[n * DD + t];
    if (t < HHD) { red_l[t] = 0.f; red_r[t] = 0.f; }
    __syncthreads();
    float acc = 0.f;
#pragma unroll
    for (int k = 0; k < DD; k++) acc = fmaf(xs[k], fcw[k * HD + t], acc);
    g_h[n * HD + t] = acc;
    int head = t >> 6, d = t & 63;
    float pl = acc * al[head * DD + d];
    float pr = acc * ar[head * DD + d];
#pragma unroll
    for (int o = 16; o > 0; o >>= 1) {
        pl += __shfl_down_sync(0xffffffffu, pl, o);
        pr += __shfl_down_sync(0xffffffffu, pr, o);
    }
    if ((t & 31) == 0) { atomicAdd(&red_l[head], pl); atomicAdd(&red_r[head], pr); }
    __syncthreads();
    if (t < HHD) { g_el[n * HHD + t] = red_l[t]; g_er[n * HHD + t] = red_r[t]; }
}

// ---------------- zero aggregation scratch ----------------
__global__ void zero_agg() {
    int i = blockIdx.x * blockDim.x + threadIdx.x;
    if (i < NN * HD) g_agg[i] = 0.f;
    if (i < NN * HHD) g_den[i] = 0.f;
}

// ---------------- build the per-layer w(r)*C(r) table ----------------
__global__ void build_table(const float* __restrict__ off,
                            const float* __restrict__ wid,
                            const float* __restrict__ w1,
                            const float* __restrict__ b1,
                            const float* __restrict__ w2,
                            const float* __restrict__ b2) {
    int i = blockIdx.x;       // 0..TBL
    int t = threadIdx.x;      // 128 threads
    __shared__ float gs[GG];
    __shared__ float hid[HIDN];
    float r = (float)i * (8.0f / (float)TBL);
    if (t < GG) {
        float w = wid[t];
        float coef = -0.5f / (w * w);
        float dr = r - off[t];
        gs[t] = expf(coef * dr * dr);
    }
    __syncthreads();
    float acc = b1[t];
#pragma unroll
    for (int g = 0; g < GG; g++) acc = fmaf(gs[g], w1[g * HD + t], acc);
    hid[t] = ssp(acc);
    __syncthreads();
    float acc2 = b2[t];
#pragma unroll 8
    for (int k = 0; k < HIDN; k++) acc2 = fmaf(hid[k], w2[k * HD + t], acc2);
    float C = 0.5f * (cosf(r * 0.39269908169872414f) + 1.0f);  // pi/8; C(8)=0
    g_T[i * HD + t] = acc2 * C;
}

// ---------------- fused edge pass: table lookup + attention + aggregate ----------------
// warp per edge, 8 edges per block
__global__ void __launch_bounds__(256) edge_pass(const int* __restrict__ src,
                                                 const int* __restrict__ dst) {
    int e = blockIdx.x * 8 + (threadIdx.x >> 5);
    int lane = threadIdx.x & 31;
    if (e >= EE) return;
    int s = src[e], d = dst[e];
    float r = g_r[e];

    // attention logits (cheap broadcast loads; all lanes compute both heads)
    float el0 = g_el[s * 2 + 0], el1 = g_el[s * 2 + 1];
    float er0 = g_er[d * 2 + 0], er1 = g_er[d * 2 + 1];
    float ev0 = el0 + er0; ev0 = ev0 > 0.f ? ev0 : 0.2f * ev0;
    float ev1 = el1 + er1; ev1 = ev1 > 0.f ? ev1 : 0.2f * ev1;
    float ex0 = expf(ev0);   // softmax w/o max-shift (shift-invariant)
    float ex1 = expf(ev1);
    if (lane == 0) atomicAdd(&g_den[d * 2 + 0], ex0);
    if (lane == 1) atomicAdd(&g_den[d * 2 + 1], ex1);

    if (r < 8.0f) {
        float u = r * TBL_SCALE;
        int i = (int)u;
        float f = u - (float)i;
        const float4* t0 = (const float4*)(g_T + i * HD);
        const float4* t1 = t0 + (HD / 4);
        float4 a = t0[lane];
        float4 b = t1[lane];
        float4 h4 = ((const float4*)(g_h + (long long)s * HD))[lane];
        float ex = (lane < 16) ? ex0 : ex1;   // j = lane*4; head = j>>6
        float4 m;
        m.x = h4.x * fmaf(f, b.x - a.x, a.x) * ex;
        m.y = h4.y * fmaf(f, b.y - a.y, a.y) * ex;
        m.z = h4.z * fmaf(f, b.z - a.z, a.z) * ex;
        m.w = h4.w * fmaf(f, b.w - a.w, a.w) * ex;
        float* dstp = g_agg + (long long)d * HD + lane * 4;
        asm volatile("red.global.add.v4.f32 [%0], {%1,%2,%3,%4};"
                     :: "l"(dstp), "f"(m.x), "f"(m.y), "f"(m.z), "f"(m.w)
                     : "memory");
    }
}

// ---------------- per-node update: normalize, ssp, 2-layer MLP, residual ----------------
__global__ void node_update(const float* __restrict__ m1,
                            const float* __restrict__ mb1,
                            const float* __restrict__ m2,
                            const float* __restrict__ mb2) {
    int n = blockIdx.x;
    int t = threadIdx.x;  // 64 threads
    __shared__ float v[HD];
    __shared__ float t1[DD];
#pragma unroll
    for (int j = t; j < HD; j += DD) {
        int head = j >> 6;
        float den = g_den[n * HHD + head];
        float a = g_agg[n * HD + j];
        a = (den > 0.f) ? a / den : 0.f;
        v[j] = ssp(a);
    }
    __syncthreads();
    float acc = mb1[t];
#pragma unroll 8
    for (int k = 0; k < HD; k++) acc = fmaf(v[k], m1[k * DD + t], acc);
    t1[t] = ssp(acc);
    __syncthreads();
    float acc2 = mb2[t];
#pragma unroll
    for (int k = 0; k < DD; k++) acc2 = fmaf(t1[k], m2[k * DD + t], acc2);
    g_x[n * DD + t] += acc2;
}

// ---------------- output head ----------------
__global__ void zero_out(float* out) {
    if (threadIdx.x < BB) out[threadIdx.x] = 0.f;
}

__global__ void out_kernel(const float* __restrict__ w1,
                           const float* __restrict__ b1,
                           const float* __restrict__ w2,
                           const float* __restrict__ b2,
                           const int* __restrict__ gid,
                           float* __restrict__ out) {
    int n = blockIdx.x;
    int t = threadIdx.x;  // 128 threads
    __shared__ float xs[DD];
    __shared__ float red[4];
    if (t < DD) xs[t] = g_x[n * DD + t];
    __syncthreads();
    float acc = b1[t];
#pragma unroll
    for (int k = 0; k < DD; k++) acc = fmaf(xs[k], w1[k * 128 + t], acc);
    float p = ssp(acc) * w2[t];
#pragma unroll
    for (int o = 16; o > 0; o >>= 1) p += __shfl_down_sync(0xffffffffu, p, o);
    if ((t & 31) == 0) red[t >> 5] = p;
    __syncthreads();
    if (t == 0) {
        float hh = red[0] + red[1] + red[2] + red[3] + b2[0];
        atomicAdd(&out[gid[n]], hh);
    }
}

extern "C" void kernel_launch(void* const* d_in, const int* in_sizes, int n_in,
                              void* d_out, int out_size) {
    const float* R    = (const float*)d_in[0];
    const int*   Z    = (const int*)d_in[1];
    const int*   src  = (const int*)d_in[2];
    const int*   dst  = (const int*)d_in[3];
    const int*   gid  = (const int*)d_in[4];
    const float* emb  = (const float*)d_in[5];
    const float* off  = (const float*)d_in[6];
    const float* wid  = (const float*)d_in[7];
    const float* fcw  = (const float*)d_in[8];
    const float* al   = (const float*)d_in[9];
    const float* ar   = (const float*)d_in[10];
    const float* fw1  = (const float*)d_in[11];
    const float* fb1  = (const float*)d_in[12];
    const float* fw2  = (const float*)d_in[13];
    const float* fb2  = (const float*)d_in[14];
    const float* m1   = (const float*)d_in[15];
    const float* mb1  = (const float*)d_in[16];
    const float* m2   = (const float*)d_in[17];
    const float* mb2  = (const float*)d_in[18];
    const float* ow1  = (const float*)d_in[19];
    const float* ob1  = (const float*)d_in[20];
    const float* ow2  = (const float*)d_in[21];
    const float* ob2  = (const float*)d_in[22];
    float* out = (float*)d_out;

    edge_geom<<<(EE + 255) / 256, 256>>>(R, src, dst);
    embed_kernel<<<(NN * DD + 255) / 256, 256>>>(Z, emb);

    for (int l = 0; l < LLAYERS; l++) {
        node_pre<<<NN, 128>>>(fcw + l * DD * HD, al + l * HHD * DD, ar + l * HHD * DD);
        zero_agg<<<(NN * HD + 255) / 256, 256>>>();
        build_table<<<TBL + 1, 128>>>(off, wid,
                                      fw1 + l * GG * HD, fb1 + l * HD,
                                      fw2 + l * HIDN * HD, fb2 + l * HD);
        edge_pass<<<(EE + 7) / 8, 256>>>(src, dst);
        node_update<<<NN, 64>>>(m1 + l * HD * DD, mb1 + l * DD,
                                m2 + l * DD * DD, mb2 + l * DD);
    }

    zero_out<<<1, 64>>>(out);
    out_kernel<<<NN, 128>>>(ow1, ob1, ow2, ob2, gid, out);
}